// round 9
// baseline (speedup 1.0000x reference)
#include <cuda_runtime.h>
#include <cstdint>

// FPS: B=2, Npb=131072, stride=32 -> M=4096 samples, 4095 serial rounds.
// 64 CTAs/batch * 256 thr * 8 pts/thr (128 CTAs: single wave, spin-safe).
// Per-round batch argmax computed BY THE L2 ATOMIC UNIT: each CTA red.max's
// key = (round<<49 | dist_bits<<17 | tail17) and red.release.add's a counter
// on ONE line per (batch, parity). EVERY warp polls the 4B counter itself
// (broadcast address, 1 wavefront/warp/iter) and consumes independently ->
// one __syncthreads per round, no warp0 serial tail. The poll loop also
// speculatively reads the key; after detect, the ordered validating key load
// and the speculative pts[idx] coord fetch are issued in parallel (the
// ordered load is what makes the result race-free; kspec almost always
// equals kfin so the coord fetch latency is hidden).

#define NBATCH 2
#define CPB    64
#define TPB    256
#define PPT    8       // CPB*TPB*PPT = 131072
#define NPB    131072
#define MSAMP  4096
#define NW     (TPB / 32)
#define FLTMAX 3.402823466e38f

typedef unsigned long long u64;

struct __align__(16) Line { u64 key; unsigned cnt; unsigned _p; u64 _pad[14]; };
__device__ Line g_line[2][NBATCH];   // [round parity][batch], 128B apart

__global__ void reset_kernel() {
    int i = threadIdx.x;
    if (i < 2 * NBATCH) {
        g_line[i >> 1][i & 1].key = 0ULL;
        g_line[i >> 1][i & 1].cnt = 0u;
    }
}

__device__ __forceinline__ u64 f2pack(float lo, float hi) {
    u64 r; asm("mov.b64 %0, {%1,%2};" : "=l"(r) : "f"(lo), "f"(hi)); return r;
}
__device__ __forceinline__ void f2unpack(float& lo, float& hi, u64 v) {
    asm("mov.b64 {%0,%1}, %2;" : "=f"(lo), "=f"(hi) : "l"(v));
}
__device__ __forceinline__ u64 addx2(u64 a, u64 b) {   // per-lane IEEE rn add
    u64 r; asm("add.rn.f32x2 %0, %1, %2;" : "=l"(r) : "l"(a), "l"(b)); return r;
}
__device__ __forceinline__ u64 mulx2(u64 a, u64 b) {   // per-lane IEEE rn mul
    u64 r; asm("mul.rn.f32x2 %0, %1, %2;" : "=l"(r) : "l"(a), "l"(b)); return r;
}
__device__ __forceinline__ void red_max_u64(u64* p, u64 v) {
    asm volatile("red.relaxed.gpu.global.max.u64 [%0], %1;" :: "l"(p), "l"(v));
}
__device__ __forceinline__ void red_add_rel(unsigned* p, unsigned v) {
    asm volatile("red.release.gpu.global.add.u32 [%0], %1;" :: "l"(p), "r"(v));
}
__device__ __forceinline__ unsigned ld_acq_u32(const unsigned* p) {
    unsigned v;
    asm volatile("ld.acquire.gpu.global.u32 %0, [%1];" : "=r"(v) : "l"(p));
    return v;
}
__device__ __forceinline__ u64 ld_rlx_u64(const u64* p) {
    u64 v;
    asm volatile("ld.relaxed.gpu.global.u64 %0, [%1];" : "=l"(v) : "l"(p));
    return v;
}

__global__ void __launch_bounds__(TPB, 1)
fps_kernel(const float4* __restrict__ pts, float* __restrict__ out)
{
    const int c    = blockIdx.x;          // CTA within batch (0..63)
    const int b    = blockIdx.y;          // batch
    const int tid  = threadIdx.x;
    const int lane = tid & 31;
    const int wid  = tid >> 5;

    const int lbase = c * (TPB * PPT);    // in-batch base index of this CTA
    const int gbase = b * NPB + lbase;
    const float4* __restrict__ bpts = pts + (size_t)b * NPB;

    // Register-resident point state; coords packed 2-per-u64 for f32x2 math.
    u64 x2[PPT / 2], y2[PPT / 2], z2[PPT / 2];
    float dist[PPT];
    unsigned tail[PPT];                   // 0x1FFFF - in_batch_idx (17 bits)
#pragma unroll
    for (int i = 0; i < PPT / 2; ++i) {
        float4 v0 = pts[gbase + (2 * i) * TPB + tid];
        float4 v1 = pts[gbase + (2 * i + 1) * TPB + tid];
        x2[i] = f2pack(v0.y, v1.y);
        y2[i] = f2pack(v0.z, v1.z);
        z2[i] = f2pack(v0.w, v1.w);
        dist[2 * i] = FLTMAX; dist[2 * i + 1] = FLTMAX;
        tail[2 * i]     = 0x1FFFFu - (unsigned)(lbase + (2 * i) * TPB + tid);
        tail[2 * i + 1] = 0x1FFFFu - (unsigned)(lbase + (2 * i + 1) * TPB + tid);
    }

    // Seed sample = point 0 of the batch (pointops convention)
    float4 p0 = bpts[0];
    float sx = p0.y, sy = p0.z, sz = p0.w;
    if (c == 0 && tid == 0)
        ((float4*)out)[(size_t)b * MSAMP] = p0;

    __shared__ unsigned s_db[NW], s_tl[NW];

    for (int t = 1; t < MSAMP; ++t) {
        // negate once (exact); x + (-s) is bit-identical to x - s in rn
        u64 nsx = f2pack(-sx, -sx);
        u64 nsy = f2pack(-sy, -sy);
        u64 nsz = f2pack(-sz, -sz);

        // ---- local dist update + per-thread argmax (bit compare == float
        // compare for non-negative f32; strict > keeps lowest idx since idx
        // ascends within the thread -> matches jnp.argmax first-max) ----
        unsigned bdb = 0u, btl = 0u;
#pragma unroll
        for (int i = 0; i < PPT / 2; ++i) {
            u64 dx = addx2(x2[i], nsx);
            u64 dy = addx2(y2[i], nsy);
            u64 dz = addx2(z2[i], nsz);
            // unfused, left-to-right (dx*dx + dy*dy) + dz*dz == reference
            u64 s = addx2(addx2(mulx2(dx, dx), mulx2(dy, dy)), mulx2(dz, dz));
            float d0, d1; f2unpack(d0, d1, s);
            float nd0 = fminf(dist[2 * i], d0);
            float nd1 = fminf(dist[2 * i + 1], d1);
            dist[2 * i] = nd0; dist[2 * i + 1] = nd1;
            unsigned db0 = __float_as_uint(nd0);
            unsigned db1 = __float_as_uint(nd1);
            if (db0 > bdb) { bdb = db0; btl = tail[2 * i]; }
            if (db1 > bdb) { bdb = db1; btl = tail[2 * i + 1]; }
        }

        // ---- warp argmax: max dist-bits, tie -> max tail (= lowest idx) ----
        unsigned m  = __reduce_max_sync(0xFFFFFFFFu, bdb);
        unsigned mt = __reduce_max_sync(0xFFFFFFFFu, (bdb == m) ? btl : 0u);
        if (lane == 0) { s_db[wid] = m; s_tl[wid] = mt; }
        __syncthreads();   // the ONLY barrier in the round

        Line* L = &g_line[t & 1][b];

        // ---- warp0: block argmax over NW warp winners, publish to L2 ----
        if (wid == 0) {
            unsigned db2 = (lane < NW) ? s_db[lane] : 0u;
            unsigned tl2 = (lane < NW) ? s_tl[lane] : 0u;
            unsigned m2  = __reduce_max_sync(0xFFFFFFFFu, db2);
            unsigned mt2 = __reduce_max_sync(0xFFFFFFFFu, (db2 == m2) ? tl2 : 0u);
            if (lane == 0) {
                u64 key = ((u64)(unsigned)t << 49) | ((u64)m2 << 17) | (u64)mt2;
                red_max_u64(&L->key, key);      // batch argmax done by L2
                red_add_rel(&L->cnt, 1u);       // release: my max visible first
            }
        }

        // ---- EVERY warp detects and consumes independently.
        // Poll only the 4B counter (broadcast address). '>=' is safe: this
        // parity line passes 'target' only after every CTA consumed round t.
        // kspec is read concurrently each iteration (speculation). ----
        const unsigned target = (unsigned)CPB * (unsigned)((t + 1) >> 1);
        unsigned cnt; u64 kspec;
        do {
            cnt   = ld_acq_u32(&L->cnt);
            kspec = ld_rlx_u64(&L->key);
        } while (cnt < target);

        // Speculative coord fetch + ordered validating key load, in parallel.
        // kfin is ordered after the successful acquire -> guaranteed final
        // (all 64 maxes happened-before their release-adds; acquire on the
        // summed counter makes them all visible). Output always uses kfin.
        unsigned idxs = 0x1FFFFu - (unsigned)(kspec & 0x1FFFFu);
        float4 w = bpts[idxs];                  // broadcast L2 hit (in flight)
        u64 kfin = ld_rlx_u64(&L->key);         // in flight concurrently
        if (kfin != kspec) {                    // rare: refetch correct coords
            unsigned idxf = 0x1FFFFu - (unsigned)(kfin & 0x1FFFFu);
            w = bpts[idxf];
        }
        sx = w.y; sy = w.z; sz = w.w;

        if (c == 0 && wid == 0 && lane == 0)
            ((float4*)out)[(size_t)b * MSAMP + t] = w;   // {b, x, y, z}
        // no second barrier: each warp proceeds with the new sample in regs
    }
}

extern "C" void kernel_launch(void* const* d_in, const int* in_sizes, int n_in,
                              void* d_out, int out_size) {
    (void)in_sizes; (void)n_in; (void)out_size;
    const float4* pts = (const float4*)d_in[0];
    reset_kernel<<<1, 32>>>();                    // clears lines each replay
    dim3 grid(CPB, NBATCH);
    fps_kernel<<<grid, TPB>>>(pts, (float*)d_out);
}

// round 11
// speedup vs baseline: 1.8058x; 1.8058x over previous
#include <cuda_runtime.h>
#include <cstdint>

// FPS: B=2, Npb=131072, stride=32 -> M=4096 samples, 4095 serial rounds.
// 64 CTAs/batch * 256 thr * 8 pts/thr (128 CTAs: single wave, spin-safe).
// Per-round batch argmax computed BY THE L2 ATOMIC UNIT: each CTA red.max's
// key = (round<<49 | dist_bits<<17 | tail17) and red.release.add's a counter
// on ONE line per (batch, parity). ONLY warp0 of each CTA polls the 4B
// counter (broadcast address; 128 polling warps total -- R5/R8 showed more
// pollers saturate the hot LTS slice and regress). The poll loop also reads
// the key speculatively; on detect, the speculative pts[idx] coord fetch and
// the ordered validating key reload are issued in parallel, overlapping the
// two ~250cyc L2 trips of the consume tail. Result always derives from the
// validated key -> deterministic. Other warps receive the new sample via
// smem + a second barrier (R7 structure).

#define NBATCH 2
#define CPB    64
#define TPB    256
#define PPT    8       // CPB*TPB*PPT = 131072
#define NPB    131072
#define MSAMP  4096
#define NW     (TPB / 32)
#define FLTMAX 3.402823466e38f

typedef unsigned long long u64;

struct __align__(16) Line { u64 key; unsigned cnt; unsigned _p; u64 _pad[14]; };
__device__ Line g_line[2][NBATCH];   // [round parity][batch], 128B apart

__global__ void reset_kernel() {
    int i = threadIdx.x;
    if (i < 2 * NBATCH) {
        g_line[i >> 1][i & 1].key = 0ULL;
        g_line[i >> 1][i & 1].cnt = 0u;
    }
}

__device__ __forceinline__ u64 f2pack(float lo, float hi) {
    u64 r; asm("mov.b64 %0, {%1,%2};" : "=l"(r) : "f"(lo), "f"(hi)); return r;
}
__device__ __forceinline__ void f2unpack(float& lo, float& hi, u64 v) {
    asm("mov.b64 {%0,%1}, %2;" : "=f"(lo), "=f"(hi) : "l"(v));
}
__device__ __forceinline__ u64 addx2(u64 a, u64 b) {   // per-lane IEEE rn add
    u64 r; asm("add.rn.f32x2 %0, %1, %2;" : "=l"(r) : "l"(a), "l"(b)); return r;
}
__device__ __forceinline__ u64 mulx2(u64 a, u64 b) {   // per-lane IEEE rn mul
    u64 r; asm("mul.rn.f32x2 %0, %1, %2;" : "=l"(r) : "l"(a), "l"(b)); return r;
}
__device__ __forceinline__ void red_max_u64(u64* p, u64 v) {
    asm volatile("red.relaxed.gpu.global.max.u64 [%0], %1;" :: "l"(p), "l"(v));
}
__device__ __forceinline__ void red_add_rel(unsigned* p, unsigned v) {
    asm volatile("red.release.gpu.global.add.u32 [%0], %1;" :: "l"(p), "r"(v));
}
__device__ __forceinline__ unsigned ld_acq_u32(const unsigned* p) {
    unsigned v;
    asm volatile("ld.acquire.gpu.global.u32 %0, [%1];" : "=r"(v) : "l"(p));
    return v;
}
__device__ __forceinline__ u64 ld_rlx_u64(const u64* p) {
    u64 v;
    asm volatile("ld.relaxed.gpu.global.u64 %0, [%1];" : "=l"(v) : "l"(p));
    return v;
}

__global__ void __launch_bounds__(TPB, 1)
fps_kernel(const float4* __restrict__ pts, float* __restrict__ out)
{
    const int c    = blockIdx.x;          // CTA within batch (0..63)
    const int b    = blockIdx.y;          // batch
    const int tid  = threadIdx.x;
    const int lane = tid & 31;
    const int wid  = tid >> 5;

    const int lbase = c * (TPB * PPT);    // in-batch base index of this CTA
    const int gbase = b * NPB + lbase;
    const float4* __restrict__ bpts = pts + (size_t)b * NPB;

    // Register-resident point state; coords packed 2-per-u64 for f32x2 math.
    u64 x2[PPT / 2], y2[PPT / 2], z2[PPT / 2];
    float dist[PPT];
    unsigned tail[PPT];                   // 0x1FFFF - in_batch_idx (17 bits)
#pragma unroll
    for (int i = 0; i < PPT / 2; ++i) {
        float4 v0 = pts[gbase + (2 * i) * TPB + tid];
        float4 v1 = pts[gbase + (2 * i + 1) * TPB + tid];
        x2[i] = f2pack(v0.y, v1.y);
        y2[i] = f2pack(v0.z, v1.z);
        z2[i] = f2pack(v0.w, v1.w);
        dist[2 * i] = FLTMAX; dist[2 * i + 1] = FLTMAX;
        tail[2 * i]     = 0x1FFFFu - (unsigned)(lbase + (2 * i) * TPB + tid);
        tail[2 * i + 1] = 0x1FFFFu - (unsigned)(lbase + (2 * i + 1) * TPB + tid);
    }

    // Seed sample = point 0 of the batch (pointops convention)
    float4 p0 = bpts[0];
    float sx = p0.y, sy = p0.z, sz = p0.w;
    if (c == 0 && tid == 0)
        ((float4*)out)[(size_t)b * MSAMP] = p0;

    __shared__ unsigned s_db[NW], s_tl[NW];
    __shared__ float    s_new[3];

    for (int t = 1; t < MSAMP; ++t) {
        // negate once (exact); x + (-s) is bit-identical to x - s in rn
        u64 nsx = f2pack(-sx, -sx);
        u64 nsy = f2pack(-sy, -sy);
        u64 nsz = f2pack(-sz, -sz);

        // ---- local dist update + per-thread argmax (bit compare == float
        // compare for non-negative f32; strict > keeps lowest idx since idx
        // ascends within the thread -> matches jnp.argmax first-max) ----
        unsigned bdb = 0u, btl = 0u;
#pragma unroll
        for (int i = 0; i < PPT / 2; ++i) {
            u64 dx = addx2(x2[i], nsx);
            u64 dy = addx2(y2[i], nsy);
            u64 dz = addx2(z2[i], nsz);
            // unfused, left-to-right (dx*dx + dy*dy) + dz*dz == reference
            u64 s = addx2(addx2(mulx2(dx, dx), mulx2(dy, dy)), mulx2(dz, dz));
            float d0, d1; f2unpack(d0, d1, s);
            float nd0 = fminf(dist[2 * i], d0);
            float nd1 = fminf(dist[2 * i + 1], d1);
            dist[2 * i] = nd0; dist[2 * i + 1] = nd1;
            unsigned db0 = __float_as_uint(nd0);
            unsigned db1 = __float_as_uint(nd1);
            if (db0 > bdb) { bdb = db0; btl = tail[2 * i]; }
            if (db1 > bdb) { bdb = db1; btl = tail[2 * i + 1]; }
        }

        // ---- warp argmax: max dist-bits, tie -> max tail (= lowest idx) ----
        unsigned m  = __reduce_max_sync(0xFFFFFFFFu, bdb);
        unsigned mt = __reduce_max_sync(0xFFFFFFFFu, (bdb == m) ? btl : 0u);
        if (lane == 0) { s_db[wid] = m; s_tl[wid] = mt; }
        __syncthreads();

        if (wid == 0) {
            // ---- block argmax over NW warp winners ----
            unsigned db2 = (lane < NW) ? s_db[lane] : 0u;
            unsigned tl2 = (lane < NW) ? s_tl[lane] : 0u;
            unsigned m2  = __reduce_max_sync(0xFFFFFFFFu, db2);
            unsigned mt2 = __reduce_max_sync(0xFFFFFFFFu, (db2 == m2) ? tl2 : 0u);

            Line* L = &g_line[t & 1][b];
            if (lane == 0) {
                u64 key = ((u64)(unsigned)t << 49) | ((u64)m2 << 17) | (u64)mt2;
                red_max_u64(&L->key, key);      // batch argmax done by L2
                red_add_rel(&L->cnt, 1u);       // release: my max visible first
            }

            // ---- detect: poll the 4B counter (broadcast address) and read
            // the key speculatively in the same iteration. '>=' is safe: this
            // parity line passes 'target' only after every CTA consumed t. ----
            const unsigned target = (unsigned)CPB * (unsigned)((t + 1) >> 1);
            unsigned cnt; u64 kspec;
            do {
                cnt   = ld_acq_u32(&L->cnt);
                kspec = ld_rlx_u64(&L->key);
            } while (cnt < target);

            // Speculative coord fetch + ordered validating key load, issued
            // in parallel (overlaps the two L2 trips of the consume tail).
            // kfin is po-after the successful acquire -> final (all 64 maxes
            // happened-before their release-adds; the summed counter makes
            // them all visible). Output always derives from kfin.
            unsigned idxs = 0x1FFFFu - (unsigned)(kspec & 0x1FFFFu);
            float4 w = bpts[idxs];              // broadcast L2 hit (in flight)
            u64 kfin = ld_rlx_u64(&L->key);     // in flight concurrently
            if (kfin != kspec) {                // rare: refetch correct coords
                unsigned idxf = 0x1FFFFu - (unsigned)(kfin & 0x1FFFFu);
                w = bpts[idxf];
            }
            if (lane == 0) {
                s_new[0] = w.y; s_new[1] = w.z; s_new[2] = w.w;
                if (c == 0)
                    ((float4*)out)[(size_t)b * MSAMP + t] = w;  // {b,x,y,z}
            }
        }
        __syncthreads();
        sx = s_new[0]; sy = s_new[1]; sz = s_new[2];
    }
}

extern "C" void kernel_launch(void* const* d_in, const int* in_sizes, int n_in,
                              void* d_out, int out_size) {
    (void)in_sizes; (void)n_in; (void)out_size;
    const float4* pts = (const float4*)d_in[0];
    reset_kernel<<<1, 32>>>();                    // clears lines each replay
    dim3 grid(CPB, NBATCH);
    fps_kernel<<<grid, TPB>>>(pts, (float*)d_out);
}